// round 17
// baseline (speedup 1.0000x reference)
#include <cuda_runtime.h>

#define FULL 0xFFFFFFFFu
typedef unsigned long long u64;

constexpr int B = 2048;
constexpr int T = 4096;
constexpr int CH = 8;              // steps per chunk (= pipeline lag)
constexpr int NCHUNK = T / CH;     // 512

__device__ __forceinline__ float tanhf_a(float x){ float y; asm("tanh.approx.f32 %0,%1;":"=f"(y):"f"(x)); return y; }
__device__ __forceinline__ u64 ffma2(u64 a, u64 b, u64 c){
    u64 d; asm("fma.rn.f32x2 %0,%1,%2,%3;" : "=l"(d) : "l"(a), "l"(b), "l"(c)); return d;
}
__device__ __forceinline__ u64 fmul2(u64 a, u64 b){
    u64 d; asm("mul.rn.f32x2 %0,%1,%2;" : "=l"(d) : "l"(a), "l"(b)); return d;
}
__device__ __forceinline__ u64 fadd2(u64 a, u64 b){
    u64 d; asm("add.rn.f32x2 %0,%1,%2;" : "=l"(d) : "l"(a), "l"(b)); return d;
}
__device__ __forceinline__ u64 pack2(float lo, float hi){
    u64 d; asm("mov.b64 %0,{%1,%2};" : "=l"(d) : "f"(lo), "f"(hi)); return d;
}
__device__ __forceinline__ void unpack2(u64 v, float& lo, float& hi){
    asm("mov.b64 {%0,%1},%2;" : "=f"(lo), "=f"(hi) : "l"(v));
}
__device__ __forceinline__ u64 dup2(float v){ return pack2(v, v); }
__device__ __forceinline__ float lo2(u64 v){ float lo, hi; unpack2(v, lo, hi); return lo; }

// ONE warp, 4 batches, TWO temporally-pipelined chains (A: L0@t, B: L1@t-8,
// register-ring handoff). R16: PIPE-AWARE schedule — every MUFU.TANH is
// separated by FMA/SHFL filler (in-order issue: back-to-back MUFUs stall the
// warp at rt=8); head computed as direct per-lane FFMA dot on dup-broadcast
// h2 (no serial shfl butterfly); head(s) deferred into iteration s+1 so the
// redist-shfl tail latency is absorbed by the next A-matvec.
// lane = (group = lane>>3, unit u = lane&7); lane computes all 4 gates of
// its unit, pair-packed (i,f),(g,o) in f32x2.
// Activations: sigmoid(z)=0.5*tanh(0.5z)+0.5, the 0.5 pre-folded in weights.
__global__ void __launch_bounds__(128, 1)
lstm2_kernel(const float* __restrict__ x,
             const float* __restrict__ Wih0, const float* __restrict__ Whh0,
             const float* __restrict__ bih0, const float* __restrict__ bhh0,
             const float* __restrict__ Wih1, const float* __restrict__ Whh1,
             const float* __restrict__ bih1, const float* __restrict__ bhh1,
             const float* __restrict__ Wlin, const float* __restrict__ blin,
             float* __restrict__ out)
{
    const int lane  = threadIdx.x & 31;
    const int gwarp = blockIdx.x * 4 + (threadIdx.x >> 5);  // 0..511
    const int u     = lane & 7;
    const int grp   = lane >> 3;
    const int base  = lane & 24;
    const int b     = gwarp * 4 + grp;                      // this lane's batch

    const float Hs = 0.5f;

    // ---- weights: pre-scaled by activation constant, pair-packed ----
    u64 whh0_if[8], whh0_go[8], wih1_if[8], wih1_go[8], whh1_if[8], whh1_go[8];
#pragma unroll
    for (int k = 0; k < 8; k++) {
        whh0_if[k] = pack2(Hs*Whh0[u*8+k],      Hs*Whh0[(8+u)*8+k]);
        whh0_go[k] = pack2(Whh0[(16+u)*8+k],    Hs*Whh0[(24+u)*8+k]);
        wih1_if[k] = pack2(Hs*Wih1[u*8+k],      Hs*Wih1[(8+u)*8+k]);
        wih1_go[k] = pack2(Wih1[(16+u)*8+k],    Hs*Wih1[(24+u)*8+k]);
        whh1_if[k] = pack2(Hs*Whh1[u*8+k],      Hs*Whh1[(8+u)*8+k]);
        whh1_go[k] = pack2(Whh1[(16+u)*8+k],    Hs*Whh1[(24+u)*8+k]);
    }
    const u64 wx_if0 = pack2(Hs*Wih0[u],    Hs*Wih0[8+u]);
    const u64 wx_go0 = pack2(Wih0[16+u],    Hs*Wih0[24+u]);
    const u64 b_if0  = pack2(Hs*(bih0[u]+bhh0[u]),      Hs*(bih0[8+u]+bhh0[8+u]));
    const u64 b_go0  = pack2((bih0[16+u]+bhh0[16+u]),   Hs*(bih0[24+u]+bhh0[24+u]));
    const u64 b_if1  = pack2(Hs*(bih1[u]+bhh1[u]),      Hs*(bih1[8+u]+bhh1[8+u]));
    const u64 b_go1  = pack2((bih1[16+u]+bhh1[16+u]),   Hs*(bih1[24+u]+bhh1[24+u]));
    float wl[8];
#pragma unroll
    for (int k = 0; k < 8; k++) wl[k] = Wlin[k];
    const float blv = blin[0];

    // ---- state ----
    u64 h1x[8], h2x[8];
#pragma unroll
    for (int k = 0; k < 8; k++) { h1x[k] = 0ull; h2x[k] = 0ull; }
    float c1 = 0.f, c2 = 0.f, pbuf = 0.f;

    // 8-step register ring: L1-input partials (per-lane produce & consume)
    u64 bufIF[CH], bufGO[CH];

    const float* xrow = x + (size_t)b * T + u;   // lane holds x[b][c*CH + u]
    float*       ob   = out + (size_t)b * T;
    float xcur = xrow[0], xnext;

    // head for the step whose h2 currently sits dup-broadcast in h2x:
    // direct per-lane dot product, two parallel FFMA chains, no shfl.
    auto headp = [&](int sidx) {
        float p0 = fmaf(wl[0], lo2(h2x[0]), blv);
        float p1 = wl[1] * lo2(h2x[1]);
        p0 = fmaf(wl[2], lo2(h2x[2]), p0);
        p1 = fmaf(wl[3], lo2(h2x[3]), p1);
        p0 = fmaf(wl[4], lo2(h2x[4]), p0);
        p1 = fmaf(wl[5], lo2(h2x[5]), p1);
        p0 = fmaf(wl[6], lo2(h2x[6]), p0);
        p1 = fmaf(wl[7], lo2(h2x[7]), p1);
        float p = p0 + p1;
        pbuf = (u == sidx) ? p : pbuf;           // bank step t in lane t&7
    };

    // emit the L1-input partial for the CURRENT h1x
    auto emit_partial = [&](u64& rifO, u64& rgoO) {
        u64 rif0 = ffma2(wih1_if[0], h1x[0], b_if1);
        u64 rgo0 = ffma2(wih1_go[0], h1x[0], b_go1);
        u64 rif1 = fmul2(wih1_if[4], h1x[4]);
        u64 rgo1 = fmul2(wih1_go[4], h1x[4]);
#pragma unroll
        for (int k = 1; k < 4; k++) {
            rif0 = ffma2(wih1_if[k], h1x[k], rif0);
            rgo0 = ffma2(wih1_go[k], h1x[k], rgo0);
        }
#pragma unroll
        for (int k = 5; k < 8; k++) {
            rif1 = ffma2(wih1_if[k], h1x[k], rif1);
            rgo1 = ffma2(wih1_go[k], h1x[k], rgo1);
        }
        rifO = fadd2(rif0, rif1);
        rgoO = fadd2(rgo0, rgo1);
    };

    // Chain-A-only step (prologue)
    auto L0only = [&](float xt, u64& rifO, u64& rgoO) {
        u64 xd   = dup2(xt);
        u64 aif0 = ffma2(wx_if0, xd, b_if0);
        u64 ago0 = ffma2(wx_go0, xd, b_go0);
        u64 aif1 = fmul2(whh0_if[4], h1x[4]);
        u64 ago1 = fmul2(whh0_go[4], h1x[4]);
#pragma unroll
        for (int k = 0; k < 4; k++) {
            aif0 = ffma2(whh0_if[k], h1x[k], aif0);
            ago0 = ffma2(whh0_go[k], h1x[k], ago0);
        }
#pragma unroll
        for (int k = 5; k < 8; k++) {
            aif1 = ffma2(whh0_if[k], h1x[k], aif1);
            ago1 = ffma2(whh0_go[k], h1x[k], ago1);
        }
        u64 aif = fadd2(aif0, aif1);
        u64 ago = fadd2(ago0, ago1);
        float zi, zf, zg, zo;
        unpack2(aif, zi, zf);
        unpack2(ago, zg, zo);
        float iv = fmaf(0.5f, tanhf_a(zi), 0.5f);
        float fv = fmaf(0.5f, tanhf_a(zf), 0.5f);
        float gv = tanhf_a(zg);
        float ov = fmaf(0.5f, tanhf_a(zo), 0.5f);
        c1 = fmaf(fv, c1, iv * gv);
        float h = ov * tanhf_a(c1);
#pragma unroll
        for (int k = 0; k < 8; k++)
            h1x[k] = dup2(__shfl_sync(FULL, h, base + k));
        emit_partial(rifO, rgoO);
    };

    // Chain-B-only step (epilogue)
    auto L1only = [&](u64 pif, u64 pgo, int s8) {
        u64 bif0 = ffma2(whh1_if[0], h2x[0], pif);
        u64 bgo0 = ffma2(whh1_go[0], h2x[0], pgo);
        u64 bif1 = fmul2(whh1_if[4], h2x[4]);
        u64 bgo1 = fmul2(whh1_go[4], h2x[4]);
#pragma unroll
        for (int k = 1; k < 4; k++) {
            bif0 = ffma2(whh1_if[k], h2x[k], bif0);
            bgo0 = ffma2(whh1_go[k], h2x[k], bgo0);
        }
#pragma unroll
        for (int k = 5; k < 8; k++) {
            bif1 = ffma2(whh1_if[k], h2x[k], bif1);
            bgo1 = ffma2(whh1_go[k], h2x[k], bgo1);
        }
        u64 aif = fadd2(bif0, bif1);
        u64 ago = fadd2(bgo0, bgo1);
        float zi, zf, zg, zo;
        unpack2(aif, zi, zf);
        unpack2(ago, zg, zo);
        float iv = fmaf(0.5f, tanhf_a(zi), 0.5f);
        float fv = fmaf(0.5f, tanhf_a(zf), 0.5f);
        float gv = tanhf_a(zg);
        float ov = fmaf(0.5f, tanhf_a(zo), 0.5f);
        c2 = fmaf(fv, c2, iv * gv);
        float h2 = ov * tanhf_a(c2);
#pragma unroll
        for (int k = 0; k < 8; k++)
            h2x[k] = dup2(__shfl_sync(FULL, h2, base + k));
        headp(s8);
    };

    // ---- prologue: chunk 0, chain A only (fills the ring) ----
    xnext = xrow[CH];
#pragma unroll
    for (int s = 0; s < CH; s++) {
        float xt = __shfl_sync(FULL, xcur, base + s);
        L0only(xt, bufIF[s], bufGO[s]);
    }
    xcur = xnext;

    // ---- main loop: A on chunk c, B on chunk c-1, pipe-aware interleave ----
    for (int c = 1; c < NCHUNK; c++) {
        xnext = (c + 1 < NCHUNK) ? xrow[(c + 1) * CH] : 0.f;
#pragma unroll
        for (int s = 0; s < CH; s++) {
            const u64 pif = bufIF[s], pgo = bufGO[s];     // chunk c-1 partial
            float xt = __shfl_sync(FULL, xcur, base + s);
            u64 xd = dup2(xt);

            // ===== A matvec (L0 @ t): pure FMA block =====
            u64 Aif0 = ffma2(wx_if0, xd, b_if0);
            u64 Ago0 = ffma2(wx_go0, xd, b_go0);
            u64 Aif1 = fmul2(whh0_if[4], h1x[4]);
            u64 Ago1 = fmul2(whh0_go[4], h1x[4]);
            Aif0 = ffma2(whh0_if[0], h1x[0], Aif0);
            Ago0 = ffma2(whh0_go[0], h1x[0], Ago0);
            Aif0 = ffma2(whh0_if[1], h1x[1], Aif0);
            Ago0 = ffma2(whh0_go[1], h1x[1], Ago0);
            Aif1 = ffma2(whh0_if[5], h1x[5], Aif1);
            Ago1 = ffma2(whh0_go[5], h1x[5], Ago1);
            Aif0 = ffma2(whh0_if[2], h1x[2], Aif0);
            Ago0 = ffma2(whh0_go[2], h1x[2], Ago0);
            Aif1 = ffma2(whh0_if[6], h1x[6], Aif1);
            Ago1 = ffma2(whh0_go[6], h1x[6], Ago1);
            Aif0 = ffma2(whh0_if[3], h1x[3], Aif0);
            Ago0 = ffma2(whh0_go[3], h1x[3], Ago0);
            Aif1 = ffma2(whh0_if[7], h1x[7], Aif1);
            Ago1 = ffma2(whh0_go[7], h1x[7], Ago1);
            u64 Aif = fadd2(Aif0, Aif1);
            u64 Ago = fadd2(Ago0, Ago1);
            float Azi, Azf, Azg, Azo;
            unpack2(Aif, Azi, Azf);
            unpack2(Ago, Azg, Azo);

            // deferred head of the previous B step (h2x still intact)
            if (s > 0) headp(s - 1);

            // ===== B matvec woven between A's gate tanhs (MUFU spacing) =====
            u64 Bif0 = ffma2(whh1_if[0], h2x[0], pif);
            u64 Bgo0 = ffma2(whh1_go[0], h2x[0], pgo);
            float Ati = tanhf_a(Azi);                      // M1
            u64 Bif1 = fmul2(whh1_if[4], h2x[4]);
            u64 Bgo1 = fmul2(whh1_go[4], h2x[4]);
            Bif0 = ffma2(whh1_if[1], h2x[1], Bif0);
            Bgo0 = ffma2(whh1_go[1], h2x[1], Bgo0);
            float Atf = tanhf_a(Azf);                      // M2
            Bif1 = ffma2(whh1_if[5], h2x[5], Bif1);
            Bgo1 = ffma2(whh1_go[5], h2x[5], Bgo1);
            Bif0 = ffma2(whh1_if[2], h2x[2], Bif0);
            Bgo0 = ffma2(whh1_go[2], h2x[2], Bgo0);
            float Agv = tanhf_a(Azg);                      // M3
            Bif1 = ffma2(whh1_if[6], h2x[6], Bif1);
            Bgo1 = ffma2(whh1_go[6], h2x[6], Bgo1);
            Bif0 = ffma2(whh1_if[3], h2x[3], Bif0);
            Bgo0 = ffma2(whh1_go[3], h2x[3], Bgo0);
            float Ato = tanhf_a(Azo);                      // M4
            Bif1 = ffma2(whh1_if[7], h2x[7], Bif1);
            Bgo1 = ffma2(whh1_go[7], h2x[7], Bgo1);
            u64 Bif = fadd2(Bif0, Bif1);
            u64 Bgo = fadd2(Bgo0, Bgo1);
            float Bzi, Bzf, Bzg, Bzo;
            unpack2(Bif, Bzi, Bzf);
            unpack2(Bgo, Bzg, Bzo);

            // ===== A cell update; B tanhs spaced by scalar fmas/shfls =====
            float Aiv = fmaf(0.5f, Ati, 0.5f);
            float Afv = fmaf(0.5f, Atf, 0.5f);
            float AG  = Aiv * Agv;
            c1 = fmaf(Afv, c1, AG);
            float Bti = tanhf_a(Bzi);                      // M5
            float Aov = fmaf(0.5f, Ato, 0.5f);
            float tc1 = tanhf_a(c1);                       // M6
            float Btf = tanhf_a(Bzf);                      // M7
            float Biv = fmaf(0.5f, Bti, 0.5f);
            float Bgv = tanhf_a(Bzg);                      // M8
            float Ah = Aov * tc1;
            float Bto = tanhf_a(Bzo);                      // M9
            // A-redist interleaved with B scalar tail
            h1x[0] = dup2(__shfl_sync(FULL, Ah, base + 0));
            float Bfv = fmaf(0.5f, Btf, 0.5f);
            h1x[1] = dup2(__shfl_sync(FULL, Ah, base + 1));
            float BG = Biv * Bgv;
            h1x[2] = dup2(__shfl_sync(FULL, Ah, base + 2));
            c2 = fmaf(Bfv, c2, BG);
            h1x[3] = dup2(__shfl_sync(FULL, Ah, base + 3));
            float tc2 = tanhf_a(c2);                       // M10
            h1x[4] = dup2(__shfl_sync(FULL, Ah, base + 4));
            float Bov = fmaf(0.5f, Bto, 0.5f);
            h1x[5] = dup2(__shfl_sync(FULL, Ah, base + 5));
            h1x[6] = dup2(__shfl_sync(FULL, Ah, base + 6));
            h1x[7] = dup2(__shfl_sync(FULL, Ah, base + 7));

            // ===== emit_partial fills tc2 latency; B-redist woven in =====
            u64 rif0 = ffma2(wih1_if[0], h1x[0], b_if1);
            u64 rgo0 = ffma2(wih1_go[0], h1x[0], b_go1);
            u64 rif1 = fmul2(wih1_if[4], h1x[4]);
            u64 rgo1 = fmul2(wih1_go[4], h1x[4]);
            rif0 = ffma2(wih1_if[1], h1x[1], rif0);
            rgo0 = ffma2(wih1_go[1], h1x[1], rgo0);
            float Bh = Bov * tc2;
            rif1 = ffma2(wih1_if[5], h1x[5], rif1);
            rgo1 = ffma2(wih1_go[5], h1x[5], rgo1);
            h2x[0] = dup2(__shfl_sync(FULL, Bh, base + 0));
            rif0 = ffma2(wih1_if[2], h1x[2], rif0);
            rgo0 = ffma2(wih1_go[2], h1x[2], rgo0);
            h2x[1] = dup2(__shfl_sync(FULL, Bh, base + 1));
            rif1 = ffma2(wih1_if[6], h1x[6], rif1);
            rgo1 = ffma2(wih1_go[6], h1x[6], rgo1);
            h2x[2] = dup2(__shfl_sync(FULL, Bh, base + 2));
            rif0 = ffma2(wih1_if[3], h1x[3], rif0);
            rgo0 = ffma2(wih1_go[3], h1x[3], rgo0);
            h2x[3] = dup2(__shfl_sync(FULL, Bh, base + 3));
            rif1 = ffma2(wih1_if[7], h1x[7], rif1);
            rgo1 = ffma2(wih1_go[7], h1x[7], rgo1);
            h2x[4] = dup2(__shfl_sync(FULL, Bh, base + 4));
            bufIF[s] = fadd2(rif0, rif1);
            h2x[5] = dup2(__shfl_sync(FULL, Bh, base + 5));
            bufGO[s] = fadd2(rgo0, rgo1);
            h2x[6] = dup2(__shfl_sync(FULL, Bh, base + 6));
            h2x[7] = dup2(__shfl_sync(FULL, Bh, base + 7));
            // head for THIS step is deferred to the next iteration (or the
            // chunk tail below), hiding the redist-shfl latency.
        }
        headp(CH - 1);                                    // last step's head
        ob[(c - 1) * CH + u] = pbuf;                      // coalesced, 8 steps
        xcur = xnext;
    }

    // ---- epilogue: chain B on the final chunk ----
#pragma unroll
    for (int s = 0; s < CH; s++)
        L1only(bufIF[s], bufGO[s], s);
    ob[(NCHUNK - 1) * CH + u] = pbuf;
}

extern "C" void kernel_launch(void* const* d_in, const int* in_sizes, int n_in,
                              void* d_out, int out_size)
{
    const float* x    = (const float*)d_in[0];
    const float* Wih0 = (const float*)d_in[1];
    const float* Whh0 = (const float*)d_in[2];
    const float* bih0 = (const float*)d_in[3];
    const float* bhh0 = (const float*)d_in[4];
    const float* Wih1 = (const float*)d_in[5];
    const float* Whh1 = (const float*)d_in[6];
    const float* bih1 = (const float*)d_in[7];
    const float* bhh1 = (const float*)d_in[8];
    const float* Wlin = (const float*)d_in[9];
    const float* blin = (const float*)d_in[10];
    float* out = (float*)d_out;

    // 4 batches per warp; 512 warps; 128-thread blocks -> warps 0-3 land on
    // SMSPs 0-3, 128 blocks over 128 SMs = 1 warp per SMSP on 86% of chip.
    const int threads = 128;
    const int blocks  = B / 16;                   // 128
    lstm2_kernel<<<blocks, threads>>>(x, Wih0, Whh0, bih0, bhh0,
                                      Wih1, Whh1, bih1, bhh1, Wlin, blin, out);
}